// round 1
// baseline (speedup 1.0000x reference)
#include <cuda_runtime.h>
#include <cstdint>
#include <cstddef>

#define KD    2048
#define NX    (512 * 2048)
#define NSTEP 100

// ---------------- device scratch (no allocations allowed) ----------------
__device__ float g_Bop[2048 * 2048];          // 16 MB: dt*beta*B, stored [n][k]
__device__ float g_nproj[NSTEP * NX];         // 419 MB: precomputed noise projections
__device__ float g_xbuf[2][NX];               // x ping-pong
__device__ float g_nlbuf[2][NX];              // nl(x) ping-pong

// ---------------- helpers ----------------
__device__ __forceinline__ float to_tf32(float x) {
    uint32_t u;
    asm("cvt.rna.tf32.f32 %0, %1;" : "=r"(u) : "f"(x));
    return __uint_as_float(u);
}

__device__ __forceinline__ float nlf(float v) {
    float v2 = v * v;
    return __fdividef(v2, 0.125f + v2);   // x^2/(gamma + x^2), gamma=0.125
}

// ---------------- precompute Bop[n][k] = 0.03*(A[n,k] - blockmean + P[n,k]) ----
__global__ void prep_B(const float* __restrict__ A, float* __restrict__ Bop) {
    __shared__ float row[2048];
    __shared__ float bsum[16];
    const int n = blockIdx.x;
    const float* Ar = A + (size_t)n * KD;

    for (int i = threadIdx.x; i < 512; i += 256) {
        reinterpret_cast<float4*>(row)[i] =
            reinterpret_cast<const float4*>(Ar)[i];
    }
    __syncthreads();

    // thread sums 8 consecutive elems (all inside one 128-block)
    float s = 0.f;
    #pragma unroll
    for (int j = 0; j < 8; j++) s += row[threadIdx.x * 8 + j];
    // reduce within groups of 16 lanes
    #pragma unroll
    for (int o = 8; o >= 1; o >>= 1) s += __shfl_down_sync(0xffffffffu, s, o, 16);
    if ((threadIdx.x & 15) == 0) bsum[threadIdx.x >> 4] = s;
    __syncthreads();

    const int nblk = n >> 7;
    for (int i = threadIdx.x; i < 512; i += 256) {
        float4 v = reinterpret_cast<const float4*>(row)[i];
        int k = i * 4;
        int kb = k >> 7;                       // same block for all 4 lanes of the float4
        float m = bsum[kb] * 0.0078125f;       // mean = sum/128
        float p = (kb == nblk) ? 0.0078125f : 0.0f;
        float4 o4;
        o4.x = 0.03f * (v.x - m + p);
        o4.y = 0.03f * (v.y - m + p);
        o4.z = 0.03f * (v.z - m + p);
        o4.w = 0.03f * (v.w - m + p);
        reinterpret_cast<float4*>(Bop + (size_t)n * KD)[i] = o4;
    }
}

// ---------------- nl(x0) init ----------------
__global__ void nl_init(const float* __restrict__ x, float* __restrict__ nlo) {
    int i = blockIdx.x * 256 + threadIdx.x;
    float4 v = reinterpret_cast<const float4*>(x)[i];
    float4 o;
    o.x = nlf(v.x); o.y = nlf(v.y); o.z = nlf(v.z); o.w = nlf(v.w);
    reinterpret_cast<float4*>(nlo)[i] = o;
}

// ---------------- tf32 NT GEMM: out[m,n] = sum_k Aop[m,k]*Bop[n,k] --------------
// OP==0: noise projection epilogue  out = scale*acc
// OP==1: step epilogue              xout = 0.97*xin + acc + nproj ; nlout = nl(xout)
template <int OP>
__global__ void __launch_bounds__(256, 1)
gemm_tf32(const float* __restrict__ Aop,
          const float* __restrict__ Bop,
          const float* __restrict__ Xin,
          const float* __restrict__ Nproj,
          float* __restrict__ Out,
          float* __restrict__ NLout,
          float scale)
{
    constexpr int BM = 128, BN = 128, BK = 16;
    constexpr int LDP = 20;                    // stride pad -> conflict-free frag loads
    __shared__ float a_s[BM][LDP];
    __shared__ float b_s[BN][LDP];

    const int tid  = threadIdx.x;
    const int lane = tid & 31;
    const int warp = tid >> 5;
    const int g    = lane >> 2;                // group id (row within mma tile)
    const int t4   = lane & 3;                 // thread-in-group (k / col pairs)
    const int warpM = warp & 3;                // 4 warps along M (32 rows each)
    const int warpN = warp >> 2;               // 2 warps along N (64 cols each)
    const int mBase = blockIdx.y * BM;
    const int nBase = blockIdx.x * BN;

    // global loader coords: 256 threads, each loads 2 float4 per operand per BK
    const int lr0 = tid >> 2;                  // 0..63
    const int lk0 = (tid & 3) * 4;             // 0,4,8,12
    const float* aptr = Aop + (size_t)(mBase + lr0) * KD + lk0;
    const float* bptr = Bop + (size_t)(nBase + lr0) * KD + lk0;

    float acc[2][8][4];
    #pragma unroll
    for (int a = 0; a < 2; a++)
        #pragma unroll
        for (int b = 0; b < 8; b++)
            #pragma unroll
            for (int c = 0; c < 4; c++) acc[a][b][c] = 0.f;

    float4 pa[2], pb[2];
    pa[0] = *reinterpret_cast<const float4*>(aptr);
    pa[1] = *reinterpret_cast<const float4*>(aptr + (size_t)64 * KD);
    pb[0] = *reinterpret_cast<const float4*>(bptr);
    pb[1] = *reinterpret_cast<const float4*>(bptr + (size_t)64 * KD);

    for (int k0 = 0; k0 < KD; k0 += BK) {
        // commit prefetched tile to smem (tf32-rounded)
        #pragma unroll
        for (int i = 0; i < 2; i++) {
            int r = lr0 + i * 64;
            a_s[r][lk0 + 0] = to_tf32(pa[i].x);
            a_s[r][lk0 + 1] = to_tf32(pa[i].y);
            a_s[r][lk0 + 2] = to_tf32(pa[i].z);
            a_s[r][lk0 + 3] = to_tf32(pa[i].w);
            b_s[r][lk0 + 0] = to_tf32(pb[i].x);
            b_s[r][lk0 + 1] = to_tf32(pb[i].y);
            b_s[r][lk0 + 2] = to_tf32(pb[i].z);
            b_s[r][lk0 + 3] = to_tf32(pb[i].w);
        }
        __syncthreads();

        // prefetch next tile into regs (latency hidden behind mma work)
        if (k0 + BK < KD) {
            int kn = k0 + BK;
            pa[0] = *reinterpret_cast<const float4*>(aptr + kn);
            pa[1] = *reinterpret_cast<const float4*>(aptr + (size_t)64 * KD + kn);
            pb[0] = *reinterpret_cast<const float4*>(bptr + kn);
            pb[1] = *reinterpret_cast<const float4*>(bptr + (size_t)64 * KD + kn);
        }

        #pragma unroll
        for (int kc = 0; kc < 2; kc++) {
            const int kk = kc * 8;
            uint32_t af[2][4];
            #pragma unroll
            for (int mt = 0; mt < 2; mt++) {
                int r = warpM * 32 + mt * 16 + g;
                af[mt][0] = __float_as_uint(a_s[r    ][kk + t4    ]);
                af[mt][1] = __float_as_uint(a_s[r + 8][kk + t4    ]);
                af[mt][2] = __float_as_uint(a_s[r    ][kk + t4 + 4]);
                af[mt][3] = __float_as_uint(a_s[r + 8][kk + t4 + 4]);
            }
            #pragma unroll
            for (int nt = 0; nt < 8; nt++) {
                int n = warpN * 64 + nt * 8 + g;
                uint32_t b0 = __float_as_uint(b_s[n][kk + t4    ]);
                uint32_t b1 = __float_as_uint(b_s[n][kk + t4 + 4]);
                #pragma unroll
                for (int mt = 0; mt < 2; mt++) {
                    asm volatile(
                        "mma.sync.aligned.m16n8k8.row.col.f32.tf32.tf32.f32 "
                        "{%0,%1,%2,%3}, {%4,%5,%6,%7}, {%8,%9}, {%0,%1,%2,%3};\n"
                        : "+f"(acc[mt][nt][0]), "+f"(acc[mt][nt][1]),
                          "+f"(acc[mt][nt][2]), "+f"(acc[mt][nt][3])
                        : "r"(af[mt][0]), "r"(af[mt][1]),
                          "r"(af[mt][2]), "r"(af[mt][3]),
                          "r"(b0), "r"(b1));
                }
            }
        }
        __syncthreads();
    }

    // epilogue
    #pragma unroll
    for (int mt = 0; mt < 2; mt++) {
        #pragma unroll
        for (int nt = 0; nt < 8; nt++) {
            int m0 = mBase + warpM * 32 + mt * 16 + g;
            int n0 = nBase + warpN * 64 + nt * 8 + t4 * 2;
            #pragma unroll
            for (int h = 0; h < 2; h++) {
                int m = m0 + h * 8;
                size_t o = (size_t)m * KD + n0;
                float v0 = acc[mt][nt][h * 2 + 0];
                float v1 = acc[mt][nt][h * 2 + 1];
                if constexpr (OP == 0) {
                    *reinterpret_cast<float2*>(Out + o) =
                        make_float2(scale * v0, scale * v1);
                } else {
                    float2 xi = *reinterpret_cast<const float2*>(Xin + o);
                    float2 np = *reinterpret_cast<const float2*>(Nproj + o);
                    float r0 = 0.97f * xi.x + v0 + np.x;
                    float r1 = 0.97f * xi.y + v1 + np.y;
                    *reinterpret_cast<float2*>(Out + o)   = make_float2(r0, r1);
                    *reinterpret_cast<float2*>(NLout + o) = make_float2(nlf(r0), nlf(r1));
                }
            }
        }
    }
}

// ---------------- launch ----------------
extern "C" void kernel_launch(void* const* d_in, const int* in_sizes, int n_in,
                              void* d_out, int out_size) {
    const float* x     = (const float*)d_in[0];   // [512, 2048]
    const float* A     = (const float*)d_in[1];   // [2048, 2048]
    const float* G     = (const float*)d_in[2];   // [2048, 2048]
    const float* noise = (const float*)d_in[3];   // [100, 512, 2048]
    float* out = (float*)d_out;

    float *Bop, *nproj, *xb, *nlb;
    cudaGetSymbolAddress((void**)&Bop,   g_Bop);
    cudaGetSymbolAddress((void**)&nproj, g_nproj);
    cudaGetSymbolAddress((void**)&xb,    g_xbuf);
    cudaGetSymbolAddress((void**)&nlb,   g_nlbuf);

    // 1. fold projection structure + dt*beta into B
    prep_B<<<2048, 256>>>(A, Bop);
    // 2. nl(x0) into ping-pong slot 1 (read by step t=0)
    nl_init<<<NX / 1024, 256>>>(x, nlb + NX);
    // 3. all 100 noise projections as one big parallel GEMM (scale = sqrt(dt)*eps)
    gemm_tf32<0><<<dim3(16, 400), 256>>>(noise, G, nullptr, nullptr,
                                         nproj, nullptr, 0.017320508075688772f);
    // 4. 100 sequential fused steps
    for (int t = 0; t < NSTEP; t++) {
        const float* nlin = nlb + (size_t)((t + 1) & 1) * NX;
        const float* xin  = (t == 0) ? x : xb + (size_t)((t + 1) & 1) * NX;
        float* xout  = (t == NSTEP - 1) ? out : xb + (size_t)(t & 1) * NX;
        float* nlout = nlb + (size_t)(t & 1) * NX;
        gemm_tf32<1><<<dim3(16, 4), 256>>>(nlin, Bop, xin,
                                           nproj + (size_t)t * NX,
                                           xout, nlout, 0.0f);
    }
}

// round 2
// speedup vs baseline: 2.2510x; 2.2510x over previous
#include <cuda_runtime.h>
#include <cstdint>
#include <cstddef>

#define KD    2048
#define NX    (512 * 2048)
#define NSTEP 100

// ---------------- device scratch (no allocations allowed) ----------------
__device__ float g_Bop[2048 * 2048];          // 16 MB: dt*beta*B (tf32-rounded), [n][k]
__device__ float g_nproj[NSTEP * NX];         // 419 MB: precomputed noise projections
__device__ float g_xbuf[2][NX];               // x ping-pong
__device__ float g_nlbuf[2][NX];              // nl(x) ping-pong (tf32-rounded)

// ---------------- helpers ----------------
__device__ __forceinline__ float to_tf32(float x) {
    uint32_t u;
    asm("cvt.rna.tf32.f32 %0, %1;" : "=r"(u) : "f"(x));
    return __uint_as_float(u);
}

__device__ __forceinline__ float nlf(float v) {
    float v2 = v * v;
    return __fdividef(v2, 0.125f + v2);   // x^2/(gamma + x^2), gamma=0.125
}

__device__ __forceinline__ void cpa16(uint32_t dst, const float* src) {
    asm volatile("cp.async.cg.shared.global [%0], [%1], 16;" :: "r"(dst), "l"(src));
}
__device__ __forceinline__ void cpa_commit() {
    asm volatile("cp.async.commit_group;");
}
template <int N>
__device__ __forceinline__ void cpa_wait() {
    asm volatile("cp.async.wait_group %0;" :: "n"(N));
}

// ---------------- precompute Bop[n][k] = tf32(0.03*(A[n,k] - blockmean + P[n,k])) ----
__global__ void prep_B(const float* __restrict__ A, float* __restrict__ Bop) {
    __shared__ float row[2048];
    __shared__ float bsum[16];
    const int n = blockIdx.x;
    const float* Ar = A + (size_t)n * KD;

    for (int i = threadIdx.x; i < 512; i += 256)
        reinterpret_cast<float4*>(row)[i] = reinterpret_cast<const float4*>(Ar)[i];
    __syncthreads();

    float s = 0.f;
    #pragma unroll
    for (int j = 0; j < 8; j++) s += row[threadIdx.x * 8 + j];
    #pragma unroll
    for (int o = 8; o >= 1; o >>= 1) s += __shfl_down_sync(0xffffffffu, s, o, 16);
    if ((threadIdx.x & 15) == 0) bsum[threadIdx.x >> 4] = s;
    __syncthreads();

    const int nblk = n >> 7;
    for (int i = threadIdx.x; i < 512; i += 256) {
        float4 v = reinterpret_cast<const float4*>(row)[i];
        int kb = (i * 4) >> 7;
        float m = bsum[kb] * 0.0078125f;
        float p = (kb == nblk) ? 0.0078125f : 0.0f;
        float4 o4;
        o4.x = to_tf32(0.03f * (v.x - m + p));
        o4.y = to_tf32(0.03f * (v.y - m + p));
        o4.z = to_tf32(0.03f * (v.z - m + p));
        o4.w = to_tf32(0.03f * (v.w - m + p));
        reinterpret_cast<float4*>(Bop + (size_t)n * KD)[i] = o4;
    }
}

// ---------------- nl(x0) init (tf32-rounded) ----------------
__global__ void nl_init(const float* __restrict__ x, float* __restrict__ nlo) {
    int i = blockIdx.x * 256 + threadIdx.x;
    float4 v = reinterpret_cast<const float4*>(x)[i];
    float4 o;
    o.x = to_tf32(nlf(v.x)); o.y = to_tf32(nlf(v.y));
    o.z = to_tf32(nlf(v.z)); o.w = to_tf32(nlf(v.w));
    reinterpret_cast<float4*>(nlo)[i] = o;
}

// ---------------- pipelined tf32 NT GEMM: out[m,n] = sum_k Aop[m,k]*Bop[n,k] ----
// 64x128x16 CTA tile, 8 warps (2M x 4N, 32x32 warp tiles), 4-stage cp.async,
// XOR-swizzled smem (conflict-free for 16B stores and frag reads).
// OP==0: out = scale*acc      OP==1: xout = 0.97*xin + acc + nproj ; nlout = tf32(nl(xout))
template <int OP>
__global__ void __launch_bounds__(256, 2)
gemm_tf32(const float* __restrict__ Aop,
          const float* __restrict__ Bop,
          const float* __restrict__ Xin,
          const float* __restrict__ Nproj,
          float* __restrict__ Out,
          float* __restrict__ NLout,
          float scale)
{
    constexpr int BM = 64, BN = 128, BK = 16, STAGES = 4;
    constexpr int NITER = KD / BK;                 // 128
    constexpr int ASZ = BM * BK;                   // 1024 floats / stage
    constexpr int BSZ = BN * BK;                   // 2048 floats / stage

    extern __shared__ float smem[];
    float* a_s = smem;                             // [STAGES][ASZ]
    float* b_s = smem + STAGES * ASZ;              // [STAGES][BSZ]
    const uint32_t smem_u32 = (uint32_t)__cvta_generic_to_shared(smem);

    const int tid  = threadIdx.x;
    const int lane = tid & 31;
    const int warp = tid >> 5;
    const int g    = lane >> 2;
    const int t4   = lane & 3;
    const int warpM = warp & 1;                    // 2 warps along M (32 rows)
    const int warpN = warp >> 1;                   // 4 warps along N (32 cols)
    const int mBase = blockIdx.y * BM;
    const int nBase = blockIdx.x * BN;

    // ---- loader coords (16B chunks), with chunk-level XOR swizzle ----
    const int alr = tid >> 2, alc = tid & 3;       // A: row 0..63, chunk 0..3
    const uint32_t aoff = alr * BK + ((alc ^ ((alr >> 1) & 3)) << 2);
    const float* gA = Aop + (size_t)(mBase + alr) * KD + alc * 4;

    const int blr0 = tid >> 2,         blc0 = tid & 3;           // B rows 0..63
    const int blr1 = (tid + 256) >> 2, blc1 = tid & 3;           // B rows 64..127
    const uint32_t boff0 = blr0 * BK + ((blc0 ^ ((blr0 >> 1) & 3)) << 2);
    const uint32_t boff1 = blr1 * BK + ((blc1 ^ ((blr1 >> 1) & 3)) << 2);
    const float* gB0 = Bop + (size_t)(nBase + blr0) * KD + blc0 * 4;
    const float* gB1 = Bop + (size_t)(nBase + blr1) * KD + blc1 * 4;

    const uint32_t aBase = smem_u32;
    const uint32_t bBase = smem_u32 + STAGES * ASZ * 4;

    float acc[2][4][4];
    #pragma unroll
    for (int a = 0; a < 2; a++)
        #pragma unroll
        for (int b = 0; b < 4; b++)
            #pragma unroll
            for (int c = 0; c < 4; c++) acc[a][b][c] = 0.f;

    // ---- prologue: fill STAGES-1 stages ----
    #pragma unroll
    for (int t = 0; t < STAGES - 1; t++) {
        int k0 = t * BK;
        cpa16(aBase + (t * ASZ + aoff) * 4, gA + k0);
        cpa16(bBase + (t * BSZ + boff0) * 4, gB0 + k0);
        cpa16(bBase + (t * BSZ + boff1) * 4, gB1 + k0);
        cpa_commit();
    }

    const int fx = ((g >> 1) & 3) << 2;            // frag-read XOR

    for (int it = 0; it < NITER; it++) {
        cpa_wait<STAGES - 2>();
        __syncthreads();

        // issue next tile
        int tnext = it + STAGES - 1;
        if (tnext < NITER) {
            int buf = tnext & (STAGES - 1);
            int k0 = tnext * BK;
            cpa16(aBase + (buf * ASZ + aoff) * 4, gA + k0);
            cpa16(bBase + (buf * BSZ + boff0) * 4, gB0 + k0);
            cpa16(bBase + (buf * BSZ + boff1) * 4, gB1 + k0);
        }
        cpa_commit();

        // compute on stage it%STAGES
        const float* aS = a_s + (it & (STAGES - 1)) * ASZ;
        const float* bS = b_s + (it & (STAGES - 1)) * BSZ;

        #pragma unroll
        for (int kc = 0; kc < 2; kc++) {
            const int kk = kc * 8;
            const int c0 = (kk + t4) ^ fx;
            const int c1 = (kk + t4 + 4) ^ fx;

            uint32_t af[2][4];
            #pragma unroll
            for (int mt = 0; mt < 2; mt++) {
                int r = warpM * 32 + mt * 16 + g;
                af[mt][0] = __float_as_uint(aS[r * BK + c0]);
                af[mt][1] = __float_as_uint(aS[(r + 8) * BK + c0]);
                af[mt][2] = __float_as_uint(aS[r * BK + c1]);
                af[mt][3] = __float_as_uint(aS[(r + 8) * BK + c1]);
            }
            #pragma unroll
            for (int nt = 0; nt < 4; nt++) {
                int n = warpN * 32 + nt * 8 + g;
                uint32_t b0 = __float_as_uint(bS[n * BK + c0]);
                uint32_t b1 = __float_as_uint(bS[n * BK + c1]);
                #pragma unroll
                for (int mt = 0; mt < 2; mt++) {
                    asm volatile(
                        "mma.sync.aligned.m16n8k8.row.col.f32.tf32.tf32.f32 "
                        "{%0,%1,%2,%3}, {%4,%5,%6,%7}, {%8,%9}, {%0,%1,%2,%3};\n"
                        : "+f"(acc[mt][nt][0]), "+f"(acc[mt][nt][1]),
                          "+f"(acc[mt][nt][2]), "+f"(acc[mt][nt][3])
                        : "r"(af[mt][0]), "r"(af[mt][1]),
                          "r"(af[mt][2]), "r"(af[mt][3]),
                          "r"(b0), "r"(b1));
                }
            }
        }
    }

    // ---- epilogue ----
    #pragma unroll
    for (int mt = 0; mt < 2; mt++) {
        #pragma unroll
        for (int nt = 0; nt < 4; nt++) {
            int m0 = mBase + warpM * 32 + mt * 16 + g;
            int n0 = nBase + warpN * 32 + nt * 8 + t4 * 2;
            #pragma unroll
            for (int h = 0; h < 2; h++) {
                int m = m0 + h * 8;
                size_t o = (size_t)m * KD + n0;
                float v0 = acc[mt][nt][h * 2 + 0];
                float v1 = acc[mt][nt][h * 2 + 1];
                if constexpr (OP == 0) {
                    *reinterpret_cast<float2*>(Out + o) =
                        make_float2(scale * v0, scale * v1);
                } else {
                    float2 xi = *reinterpret_cast<const float2*>(Xin + o);
                    float2 np = *reinterpret_cast<const float2*>(Nproj + o);
                    float r0 = 0.97f * xi.x + v0 + np.x;
                    float r1 = 0.97f * xi.y + v1 + np.y;
                    *reinterpret_cast<float2*>(Out + o)   = make_float2(r0, r1);
                    *reinterpret_cast<float2*>(NLout + o) =
                        make_float2(to_tf32(nlf(r0)), to_tf32(nlf(r1)));
                }
            }
        }
    }
}

// ---------------- launch ----------------
extern "C" void kernel_launch(void* const* d_in, const int* in_sizes, int n_in,
                              void* d_out, int out_size) {
    const float* x     = (const float*)d_in[0];   // [512, 2048]
    const float* A     = (const float*)d_in[1];   // [2048, 2048]
    const float* G     = (const float*)d_in[2];   // [2048, 2048]
    const float* noise = (const float*)d_in[3];   // [100, 512, 2048]
    float* out = (float*)d_out;

    float *Bop, *nproj, *xb, *nlb;
    cudaGetSymbolAddress((void**)&Bop,   g_Bop);
    cudaGetSymbolAddress((void**)&nproj, g_nproj);
    cudaGetSymbolAddress((void**)&xb,    g_xbuf);
    cudaGetSymbolAddress((void**)&nlb,   g_nlbuf);

    constexpr int SMEMSZ = 4 * (64 + 128) * 16 * 4;   // 49152 B
    static bool attr_done = false;
    if (!attr_done) {
        cudaFuncSetAttribute(gemm_tf32<0>, cudaFuncAttributeMaxDynamicSharedMemorySize, SMEMSZ);
        cudaFuncSetAttribute(gemm_tf32<1>, cudaFuncAttributeMaxDynamicSharedMemorySize, SMEMSZ);
        attr_done = true;
    }

    // 1. fold projection structure + dt*beta into B (tf32-rounded)
    prep_B<<<2048, 256>>>(A, Bop);
    // 2. nl(x0) into ping-pong slot 1
    nl_init<<<NX / 1024, 256>>>(x, nlb + NX);
    // 3. all 100 noise projections in one parallel GEMM (scale = sqrt(dt)*eps)
    gemm_tf32<0><<<dim3(16, 800), 256, SMEMSZ>>>(noise, G, nullptr, nullptr,
                                                 nproj, nullptr, 0.017320508075688772f);
    // 4. 100 sequential fused steps
    for (int t = 0; t < NSTEP; t++) {
        const float* nlin = nlb + (size_t)((t + 1) & 1) * NX;
        const float* xin  = (t == 0) ? x : xb + (size_t)((t + 1) & 1) * NX;
        float* xout  = (t == NSTEP - 1) ? out : xb + (size_t)(t & 1) * NX;
        float* nlout = nlb + (size_t)(t & 1) * NX;
        gemm_tf32<1><<<dim3(16, 8), 256, SMEMSZ>>>(nlin, Bop, xin,
                                                   nproj + (size_t)t * NX,
                                                   xout, nlout, 0.0f);
    }
}

// round 12
// speedup vs baseline: 2.2521x; 1.0005x over previous
#include <cuda_runtime.h>
#include <cstdint>
#include <cstddef>

#define KD    2048
#define NX    (512 * 2048)
#define NSTEP 100

// ---------------- device scratch (no allocations allowed) ----------------
__device__ float g_Bop[2048 * 2048];          // 16 MB: dt*beta*B (tf32-rounded), [n][k]
__device__ float g_nproj[(size_t)NSTEP * NX]; // 419 MB: precomputed noise projections
__device__ float g_part[2][NX];               // 8 MB: split-K partials
__device__ float g_xbuf[2][NX];               // x ping-pong
__device__ float g_nlbuf[2][NX];              // nl(x) ping-pong (tf32-rounded)

// ---------------- helpers ----------------
__device__ __forceinline__ float to_tf32(float x) {
    uint32_t u;
    asm("cvt.rna.tf32.f32 %0, %1;" : "=r"(u) : "f"(x));
    return __uint_as_float(u);
}

__device__ __forceinline__ float nlf(float v) {
    float v2 = v * v;
    return __fdividef(v2, 0.125f + v2);   // x^2/(gamma + x^2), gamma=0.125
}

__device__ __forceinline__ void cpa16(uint32_t dst, const float* src) {
    asm volatile("cp.async.cg.shared.global [%0], [%1], 16;" :: "r"(dst), "l"(src));
}
__device__ __forceinline__ void cpa_commit() {
    asm volatile("cp.async.commit_group;");
}
template <int N>
__device__ __forceinline__ void cpa_wait() {
    asm volatile("cp.async.wait_group %0;" :: "n"(N));
}

// ---------------- precompute Bop[n][k] = tf32(0.03*(A[n,k] - blockmean + P[n,k])) ----
__global__ void prep_B(const float* __restrict__ A, float* __restrict__ Bop) {
    __shared__ float row[2048];
    __shared__ float bsum[16];
    const int n = blockIdx.x;
    const float* Ar = A + (size_t)n * KD;

    for (int i = threadIdx.x; i < 512; i += 256)
        reinterpret_cast<float4*>(row)[i] = reinterpret_cast<const float4*>(Ar)[i];
    __syncthreads();

    float s = 0.f;
    #pragma unroll
    for (int j = 0; j < 8; j++) s += row[threadIdx.x * 8 + j];
    #pragma unroll
    for (int o = 8; o >= 1; o >>= 1) s += __shfl_down_sync(0xffffffffu, s, o, 16);
    if ((threadIdx.x & 15) == 0) bsum[threadIdx.x >> 4] = s;
    __syncthreads();

    const int nblk = n >> 7;
    for (int i = threadIdx.x; i < 512; i += 256) {
        float4 v = reinterpret_cast<const float4*>(row)[i];
        int kb = (i * 4) >> 7;
        float m = bsum[kb] * 0.0078125f;
        float p = (kb == nblk) ? 0.0078125f : 0.0f;
        float4 o4;
        o4.x = to_tf32(0.03f * (v.x - m + p));
        o4.y = to_tf32(0.03f * (v.y - m + p));
        o4.z = to_tf32(0.03f * (v.z - m + p));
        o4.w = to_tf32(0.03f * (v.w - m + p));
        reinterpret_cast<float4*>(Bop + (size_t)n * KD)[i] = o4;
    }
}

// ---------------- nl(x0) init (tf32-rounded) ----------------
__global__ void nl_init(const float* __restrict__ x, float* __restrict__ nlo) {
    int i = blockIdx.x * 256 + threadIdx.x;
    float4 v = reinterpret_cast<const float4*>(x)[i];
    float4 o;
    o.x = to_tf32(nlf(v.x)); o.y = to_tf32(nlf(v.y));
    o.z = to_tf32(nlf(v.z)); o.w = to_tf32(nlf(v.w));
    reinterpret_cast<float4*>(nlo)[i] = o;
}

// ======== pipelined tf32 NT GEMM core (R2-proven), parameterized K range ========
// Computes acc[m,n] = sum_{k in [kbase, kbase+KLEN)} Aop[m,k]*Bop[n,k]
// 64x128 CTA tile, BK=16, 4-stage cp.async, XOR-swizzled smem, 8 warps (2Mx4N).
// KLEN is a template param so the loop trip count stays compile-time.
template <int KLEN>
struct GemmCore {
    float acc[2][4][4];

    __device__ __forceinline__ void run(const float* __restrict__ Aop,
                                        const float* __restrict__ Bop,
                                        int mBase, int nBase, int kbase,
                                        float* smem) {
        constexpr int BM = 64, BN = 128, BK = 16, STAGES = 4;
        constexpr int NITER = KLEN / BK;
        constexpr int ASZ = BM * BK;
        constexpr int BSZ = BN * BK;

        float* a_s = smem;
        float* b_s = smem + STAGES * ASZ;
        const uint32_t smem_u32 = (uint32_t)__cvta_generic_to_shared(smem);

        const int tid  = threadIdx.x;
        const int lane = tid & 31;
        const int g    = lane >> 2;
        const int t4   = lane & 3;
        const int warp = tid >> 5;
        const int warpM = warp & 1;
        const int warpN = warp >> 1;

        const int alr = tid >> 2, alc = tid & 3;
        const uint32_t aoff = alr * BK + ((alc ^ ((alr >> 1) & 3)) << 2);
        const float* gA = Aop + (size_t)(mBase + alr) * KD + kbase + alc * 4;

        const int blr0 = tid >> 2;
        const int blr1 = (tid + 256) >> 2;
        const uint32_t boff0 = blr0 * BK + ((alc ^ ((blr0 >> 1) & 3)) << 2);
        const uint32_t boff1 = blr1 * BK + ((alc ^ ((blr1 >> 1) & 3)) << 2);
        const float* gB0 = Bop + (size_t)(nBase + blr0) * KD + kbase + alc * 4;
        const float* gB1 = Bop + (size_t)(nBase + blr1) * KD + kbase + alc * 4;

        const uint32_t aB = smem_u32;
        const uint32_t bB = smem_u32 + STAGES * ASZ * 4;

        #pragma unroll
        for (int a = 0; a < 2; a++)
            #pragma unroll
            for (int b = 0; b < 4; b++)
                #pragma unroll
                for (int c = 0; c < 4; c++) acc[a][b][c] = 0.f;

        #pragma unroll
        for (int t = 0; t < STAGES - 1; t++) {
            int k0 = t * BK;
            cpa16(aB + (t * ASZ + aoff) * 4, gA + k0);
            cpa16(bB + (t * BSZ + boff0) * 4, gB0 + k0);
            cpa16(bB + (t * BSZ + boff1) * 4, gB1 + k0);
            cpa_commit();
        }

        const int fx = ((g >> 1) & 3) << 2;

        for (int it = 0; it < NITER; it++) {
            cpa_wait<STAGES - 2>();
            __syncthreads();

            int tnext = it + STAGES - 1;
            if (tnext < NITER) {
                int buf = tnext & (STAGES - 1);
                int k0 = tnext * BK;
                cpa16(aB + (buf * ASZ + aoff) * 4, gA + k0);
                cpa16(bB + (buf * BSZ + boff0) * 4, gB0 + k0);
                cpa16(bB + (buf * BSZ + boff1) * 4, gB1 + k0);
            }
            cpa_commit();

            const float* aS = a_s + (it & (STAGES - 1)) * ASZ;
            const float* bS = b_s + (it & (STAGES - 1)) * BSZ;

            #pragma unroll
            for (int kc = 0; kc < 2; kc++) {
                const int kk = kc * 8;
                const int c0 = (kk + t4) ^ fx;
                const int c1 = (kk + t4 + 4) ^ fx;

                uint32_t af[2][4];
                #pragma unroll
                for (int mt = 0; mt < 2; mt++) {
                    int r = warpM * 32 + mt * 16 + g;
                    af[mt][0] = __float_as_uint(aS[r * BK + c0]);
                    af[mt][1] = __float_as_uint(aS[(r + 8) * BK + c0]);
                    af[mt][2] = __float_as_uint(aS[r * BK + c1]);
                    af[mt][3] = __float_as_uint(aS[(r + 8) * BK + c1]);
                }
                #pragma unroll
                for (int nt = 0; nt < 4; nt++) {
                    int n = warpN * 32 + nt * 8 + g;
                    uint32_t b0 = __float_as_uint(bS[n * BK + c0]);
                    uint32_t b1 = __float_as_uint(bS[n * BK + c1]);
                    #pragma unroll
                    for (int mt = 0; mt < 2; mt++) {
                        asm volatile(
                            "mma.sync.aligned.m16n8k8.row.col.f32.tf32.tf32.f32 "
                            "{%0,%1,%2,%3}, {%4,%5,%6,%7}, {%8,%9}, {%0,%1,%2,%3};\n"
                            : "+f"(acc[mt][nt][0]), "+f"(acc[mt][nt][1]),
                              "+f"(acc[mt][nt][2]), "+f"(acc[mt][nt][3])
                            : "r"(af[mt][0]), "r"(af[mt][1]),
                              "r"(af[mt][2]), "r"(af[mt][3]),
                              "r"(b0), "r"(b1));
                    }
                }
            }
        }
    }
};

// ---------------- noise GEMM: nproj = scale * (noise @ G^T), full K ----------------
__global__ void __launch_bounds__(256, 2)
gemm_noise(const float* __restrict__ Aop, const float* __restrict__ Bop,
           float* __restrict__ Out, float scale)
{
    extern __shared__ float smem[];
    GemmCore<KD> core;
    const int mBase = blockIdx.y * 64;
    const int nBase = blockIdx.x * 128;
    core.run(Aop, Bop, mBase, nBase, 0, smem);

    const int lane = threadIdx.x & 31;
    const int warp = threadIdx.x >> 5;
    const int g = lane >> 2, t4 = lane & 3;
    const int warpM = warp & 1, warpN = warp >> 1;

    #pragma unroll
    for (int mt = 0; mt < 2; mt++)
        #pragma unroll
        for (int nt = 0; nt < 4; nt++) {
            int m0 = mBase + warpM * 32 + mt * 16 + g;
            int n0 = nBase + warpN * 32 + nt * 8 + t4 * 2;
            #pragma unroll
            for (int h = 0; h < 2; h++) {
                size_t o = (size_t)(m0 + h * 8) * KD + n0;
                *reinterpret_cast<float2*>(Out + o) =
                    make_float2(scale * core.acc[mt][nt][h * 2 + 0],
                                scale * core.acc[mt][nt][h * 2 + 1]);
            }
        }
}

// ---------------- step GEMM, split-K=2: partial z over K-half ----------------
// z=0 folds 0.97*x + nproj into its partial.
__global__ void __launch_bounds__(256, 2)
gemm_step(const float* __restrict__ Aop, const float* __restrict__ Bop,
          const float* __restrict__ Xin, const float* __restrict__ Nproj,
          float* __restrict__ P0, float* __restrict__ P1)
{
    extern __shared__ float smem[];
    GemmCore<KD / 2> core;
    const int mBase = blockIdx.y * 64;
    const int nBase = blockIdx.x * 128;
    const int kbase = blockIdx.z << 10;           // 0 or 1024
    core.run(Aop, Bop, mBase, nBase, kbase, smem);

    const int lane = threadIdx.x & 31;
    const int warp = threadIdx.x >> 5;
    const int g = lane >> 2, t4 = lane & 3;
    const int warpM = warp & 1, warpN = warp >> 1;

    float* O = blockIdx.z ? P1 : P0;
    #pragma unroll
    for (int mt = 0; mt < 2; mt++)
        #pragma unroll
        for (int nt = 0; nt < 4; nt++) {
            int m0 = mBase + warpM * 32 + mt * 16 + g;
            int n0 = nBase + warpN * 32 + nt * 8 + t4 * 2;
            #pragma unroll
            for (int h = 0; h < 2; h++) {
                size_t o = (size_t)(m0 + h * 8) * KD + n0;
                float v0 = core.acc[mt][nt][h * 2 + 0];
                float v1 = core.acc[mt][nt][h * 2 + 1];
                if (blockIdx.z == 0) {
                    float2 xi = *reinterpret_cast<const float2*>(Xin + o);
                    float2 np = *reinterpret_cast<const float2*>(Nproj + o);
                    v0 += 0.97f * xi.x + np.x;
                    v1 += 0.97f * xi.y + np.y;
                }
                *reinterpret_cast<float2*>(O + o) = make_float2(v0, v1);
            }
        }
}

// ---------------- split-K combine + nl ----------------
__global__ void combine(const float* __restrict__ p0, const float* __restrict__ p1,
                        float* __restrict__ xout, float* __restrict__ nlout) {
    int i = blockIdx.x * 256 + threadIdx.x;
    float4 a = reinterpret_cast<const float4*>(p0)[i];
    float4 b = reinterpret_cast<const float4*>(p1)[i];
    float4 xo, nl;
    xo.x = a.x + b.x; xo.y = a.y + b.y; xo.z = a.z + b.z; xo.w = a.w + b.w;
    nl.x = to_tf32(nlf(xo.x)); nl.y = to_tf32(nlf(xo.y));
    nl.z = to_tf32(nlf(xo.z)); nl.w = to_tf32(nlf(xo.w));
    reinterpret_cast<float4*>(xout)[i]  = xo;
    reinterpret_cast<float4*>(nlout)[i] = nl;
}

// ---------------- launch ----------------
extern "C" void kernel_launch(void* const* d_in, const int* in_sizes, int n_in,
                              void* d_out, int out_size) {
    const float* x     = (const float*)d_in[0];   // [512, 2048]
    const float* A     = (const float*)d_in[1];   // [2048, 2048]
    const float* G     = (const float*)d_in[2];   // [2048, 2048]
    const float* noise = (const float*)d_in[3];   // [100, 512, 2048]
    float* out = (float*)d_out;

    float *Bop, *nproj, *part, *xb, *nlb;
    cudaGetSymbolAddress((void**)&Bop,   g_Bop);
    cudaGetSymbolAddress((void**)&nproj, g_nproj);
    cudaGetSymbolAddress((void**)&part,  g_part);
    cudaGetSymbolAddress((void**)&xb,    g_xbuf);
    cudaGetSymbolAddress((void**)&nlb,   g_nlbuf);

    constexpr int SMEMSZ = 4 * (64 + 128) * 16 * 4;   // 49152 B
    static bool attr_done = false;
    if (!attr_done) {
        cudaFuncSetAttribute(gemm_noise, cudaFuncAttributeMaxDynamicSharedMemorySize, SMEMSZ);
        cudaFuncSetAttribute(gemm_step,  cudaFuncAttributeMaxDynamicSharedMemorySize, SMEMSZ);
        attr_done = true;
    }

    // 1. fold projection structure + dt*beta into B (tf32-rounded)
    prep_B<<<2048, 256>>>(A, Bop);
    // 2. nl(x0) into ping-pong slot 1
    nl_init<<<NX / 1024, 256>>>(x, nlb + NX);
    // 3. all 100 noise projections in one parallel GEMM (scale = sqrt(dt)*eps)
    gemm_noise<<<dim3(16, 800), 256, SMEMSZ>>>(noise, G, nproj, 0.017320508075688772f);
    // 4. 100 sequential steps: split-K=2 GEMM (256 CTAs) + combine
    for (int t = 0; t < NSTEP; t++) {
        const float* nlin = nlb + (size_t)((t + 1) & 1) * NX;
        const float* xin  = (t == 0) ? x : xb + (size_t)((t + 1) & 1) * NX;
        float* xout  = (t == NSTEP - 1) ? out : xb + (size_t)(t & 1) * NX;
        float* nlout = nlb + (size_t)(t & 1) * NX;
        gemm_step<<<dim3(16, 8, 2), 256, SMEMSZ>>>(nlin, Bop, xin,
                                                   nproj + (size_t)t * NX,
                                                   part, part + NX);
        combine<<<NX / 1024, 256>>>(part, part + NX, xout, nlout);
    }
}